// round 2
// baseline (speedup 1.0000x reference)
#include <cuda_runtime.h>

// Problem constants: B=4, SQ=SKV=2048, C=1024 (all fp32)
#define BATCH 4
#define SEQ   2048
#define CH    1024

#define BM 128
#define BN 128
#define BK 16
#define TM 8
#define TN 8

// Scratch (device globals — allocation-free per harness rules)
__device__ float g_Q[BATCH * SEQ * CH];      // 32 MB
__device__ float g_K[BATCH * SEQ * CH];      // 32 MB
__device__ float g_V[BATCH * SEQ * CH];      // 32 MB
__device__ float g_S[BATCH * SEQ * SEQ];     // 64 MB
__device__ float g_A[BATCH * SEQ * CH];      // 32 MB

// C[m,n] = sum_k (A[m,k] (+ A2[m,k])) * B[n,k]  (+ bias[n])
// A: [M,K] row-major, B: [N,K] row-major (GEMM-NT). Batched via blockIdx.z strides.
__global__ __launch_bounds__(256) void gemm_nt(
    const float* __restrict__ A, const float* __restrict__ A2,
    const float* __restrict__ Bm, const float* __restrict__ bias,
    float* __restrict__ Cm,
    int M, int N, int K,
    long long az, long long bz, long long cz)
{
    __shared__ float As[BK][BM];
    __shared__ float Bs[BK][BN];

    const int z = blockIdx.z;
    const float* Ab  = A  + (long long)z * az;
    const float* A2b = A2 ? (A2 + (long long)z * az) : nullptr;
    const float* Bb  = Bm + (long long)z * bz;
    float*       Cb  = Cm + (long long)z * cz;

    const int tid = threadIdx.x;
    const int m0 = blockIdx.y * BM;
    const int n0 = blockIdx.x * BN;
    const int ty = tid / 16;
    const int tx = tid % 16;

    float acc[TM][TN];
    #pragma unroll
    for (int i = 0; i < TM; i++)
        #pragma unroll
        for (int j = 0; j < TN; j++) acc[i][j] = 0.0f;

    for (int k0 = 0; k0 < K; k0 += BK) {
        // Load tiles: 512 float4 per matrix, 2 per thread
        #pragma unroll
        for (int l = 0; l < 2; l++) {
            int f   = tid + l * 256;
            int row = f >> 2;          // 0..127
            int kc  = (f & 3) * 4;     // 0,4,8,12
            float4 v = *(const float4*)(Ab + (long long)(m0 + row) * K + k0 + kc);
            if (A2b) {
                float4 w = *(const float4*)(A2b + (long long)(m0 + row) * K + k0 + kc);
                v.x += w.x; v.y += w.y; v.z += w.z; v.w += w.w;
            }
            As[kc + 0][row] = v.x; As[kc + 1][row] = v.y;
            As[kc + 2][row] = v.z; As[kc + 3][row] = v.w;

            float4 u = *(const float4*)(Bb + (long long)(n0 + row) * K + k0 + kc);
            Bs[kc + 0][row] = u.x; Bs[kc + 1][row] = u.y;
            Bs[kc + 2][row] = u.z; Bs[kc + 3][row] = u.w;
        }
        __syncthreads();

        #pragma unroll
        for (int k = 0; k < BK; k++) {
            float ra[TM], rb[TN];
            #pragma unroll
            for (int i = 0; i < TM; i++) ra[i] = As[k][ty * TM + i];
            #pragma unroll
            for (int j = 0; j < TN; j++) rb[j] = Bs[k][tx * TN + j];
            #pragma unroll
            for (int i = 0; i < TM; i++)
                #pragma unroll
                for (int j = 0; j < TN; j++)
                    acc[i][j] = fmaf(ra[i], rb[j], acc[i][j]);
        }
        __syncthreads();
    }

    #pragma unroll
    for (int i = 0; i < TM; i++) {
        int m = m0 + ty * TM + i;
        #pragma unroll
        for (int j = 0; j < TN; j += 4) {
            int n = n0 + tx * TN + j;
            float4 v;
            v.x = acc[i][j + 0]; v.y = acc[i][j + 1];
            v.z = acc[i][j + 2]; v.w = acc[i][j + 3];
            if (bias) {
                v.x += bias[n + 0]; v.y += bias[n + 1];
                v.z += bias[n + 2]; v.w += bias[n + 3];
            }
            *(float4*)(Cb + (long long)m * N + n) = v;
        }
    }
}

// C[m,n] = sum_k A[m,k] * B[k,n]   (GEMM-NN, for P @ V). Batched via blockIdx.z.
__global__ __launch_bounds__(256) void gemm_nn(
    const float* __restrict__ A, const float* __restrict__ Bm,
    float* __restrict__ Cm,
    int M, int N, int K,
    long long az, long long bz, long long cz)
{
    __shared__ float As[BK][BM];
    __shared__ float Bs[BK][BN];

    const int z = blockIdx.z;
    const float* Ab = A  + (long long)z * az;
    const float* Bb = Bm + (long long)z * bz;
    float*       Cb = Cm + (long long)z * cz;

    const int tid = threadIdx.x;
    const int m0 = blockIdx.y * BM;
    const int n0 = blockIdx.x * BN;
    const int ty = tid / 16;
    const int tx = tid % 16;

    float acc[TM][TN];
    #pragma unroll
    for (int i = 0; i < TM; i++)
        #pragma unroll
        for (int j = 0; j < TN; j++) acc[i][j] = 0.0f;

    for (int k0 = 0; k0 < K; k0 += BK) {
        #pragma unroll
        for (int l = 0; l < 2; l++) {
            int f   = tid + l * 256;
            // A tile [BM][BK] -> As[k][m] (transposed store)
            int row = f >> 2;
            int kc  = (f & 3) * 4;
            float4 v = *(const float4*)(Ab + (long long)(m0 + row) * K + k0 + kc);
            As[kc + 0][row] = v.x; As[kc + 1][row] = v.y;
            As[kc + 2][row] = v.z; As[kc + 3][row] = v.w;

            // B tile [BK][BN] -> Bs[k][n] (direct, coalesced)
            int krow = f >> 5;          // 0..15
            int nc   = (f & 31) * 4;    // 0..124
            float4 u = *(const float4*)(Bb + (long long)(k0 + krow) * N + n0 + nc);
            *(float4*)&Bs[krow][nc] = u;
        }
        __syncthreads();

        #pragma unroll
        for (int k = 0; k < BK; k++) {
            float ra[TM], rb[TN];
            #pragma unroll
            for (int i = 0; i < TM; i++) ra[i] = As[k][ty * TM + i];
            #pragma unroll
            for (int j = 0; j < TN; j++) rb[j] = Bs[k][tx * TN + j];
            #pragma unroll
            for (int i = 0; i < TM; i++)
                #pragma unroll
                for (int j = 0; j < TN; j++)
                    acc[i][j] = fmaf(ra[i], rb[j], acc[i][j]);
        }
        __syncthreads();
    }

    #pragma unroll
    for (int i = 0; i < TM; i++) {
        int m = m0 + ty * TM + i;
        #pragma unroll
        for (int j = 0; j < TN; j += 4) {
            int n = n0 + tx * TN + j;
            float4 v;
            v.x = acc[i][j + 0]; v.y = acc[i][j + 1];
            v.z = acc[i][j + 2]; v.w = acc[i][j + 3];
            *(float4*)(Cb + (long long)m * N + n) = v;
        }
    }
}

// In-place row softmax of softmax(scale * s) over `cols` columns. One block per row.
__global__ __launch_bounds__(256) void softmax_rows(
    float* __restrict__ S, int cols, float scale)
{
    float* p = S + (long long)blockIdx.x * cols;
    const int tid = threadIdx.x;
    __shared__ float red[256];

    float m = -1e30f;
    for (int i = tid; i < cols; i += 256) m = fmaxf(m, p[i]);
    red[tid] = m; __syncthreads();
    for (int s = 128; s > 0; s >>= 1) {
        if (tid < s) red[tid] = fmaxf(red[tid], red[tid + s]);
        __syncthreads();
    }
    m = red[0];
    __syncthreads();

    float sum = 0.0f;
    for (int i = tid; i < cols; i += 256) {
        float e = __expf((p[i] - m) * scale);
        p[i] = e;
        sum += e;
    }
    red[tid] = sum; __syncthreads();
    for (int s = 128; s > 0; s >>= 1) {
        if (tid < s) red[tid] += red[tid + s];
        __syncthreads();
    }
    float inv = 1.0f / red[0];
    for (int i = tid; i < cols; i += 256) p[i] *= inv;
}

extern "C" void kernel_launch(void* const* d_in, const int* in_sizes, int n_in,
                              void* d_out, int out_size)
{
    const float* x  = (const float*)d_in[0];  // [B, SQ, C]
    const float* ce = (const float*)d_in[1];  // [B, SKV, C]
    const float* Wq = (const float*)d_in[2];
    const float* bq = (const float*)d_in[3];
    const float* Wk = (const float*)d_in[4];
    const float* bk = (const float*)d_in[5];
    const float* Wv = (const float*)d_in[6];
    const float* bv = (const float*)d_in[7];
    const float* Wo = (const float*)d_in[8];
    const float* bo = (const float*)d_in[9];
    float* out = (float*)d_out;

    float *Q, *Kb, *V, *S, *Att;
    cudaGetSymbolAddress((void**)&Q,   g_Q);
    cudaGetSymbolAddress((void**)&Kb,  g_K);
    cudaGetSymbolAddress((void**)&V,   g_V);
    cudaGetSymbolAddress((void**)&S,   g_S);
    cudaGetSymbolAddress((void**)&Att, g_A);

    const int M = BATCH * SEQ;           // 8192 rows for projections
    dim3 thr(256);

    // Q/K/V projections: [8192,1024] = in @ W^T + b
    dim3 gproj(CH / BN, M / BM, 1);
    gemm_nt<<<gproj, thr>>>(x,  nullptr, Wq, bq, Q,  M, CH, CH, 0, 0, 0);
    gemm_nt<<<gproj, thr>>>(ce, nullptr, Wk, bk, Kb, M, CH, CH, 0, 0, 0);
    gemm_nt<<<gproj, thr>>>(ce, nullptr, Wv, bv, V,  M, CH, CH, 0, 0, 0);

    // scores[b] = Q[b] @ K[b]^T  (per-batch NT GEMM)
    dim3 gsc(SEQ / BN, SEQ / BM, BATCH);
    gemm_nt<<<gsc, thr>>>(Q, nullptr, Kb, nullptr, S,
                          SEQ, SEQ, CH,
                          (long long)SEQ * CH, (long long)SEQ * CH,
                          (long long)SEQ * SEQ);

    // softmax(scale * scores) in place, per row
    softmax_rows<<<BATCH * SEQ, 256>>>(S, SEQ, 0.03125f /* 1/sqrt(1024) */);

    // attended[b] = P[b] @ V[b]  (per-batch NN GEMM)
    dim3 gpv(CH / BN, SEQ / BM, BATCH);
    gemm_nn<<<gpv, thr>>>(S, V, Att,
                          SEQ, CH, SEQ,
                          (long long)SEQ * SEQ, (long long)SEQ * CH,
                          (long long)SEQ * CH);

    // out = (x + attended) @ Wo^T + bo   (residual fused into A-load)
    gemm_nt<<<gproj, thr>>>(Att, x, Wo, bo, out, M, CH, CH, 0, 0, 0);
}

// round 5
// speedup vs baseline: 3.1497x; 3.1497x over previous
#include <cuda_runtime.h>
#include <cstdint>

#define BATCH 4
#define SEQ   2048
#define CH    1024

#define BM 128
#define BN 128
#define BK 32
#define STAGES 4
#define PAD 36            // floats per smem row (32 data + 4 pad) -> conflict-free frags
#define TILE_F (BM * PAD) // floats per stage per operand

// ---------------- scratch (device globals; allocation-free) ----------------
__device__ float g_Q [BATCH*SEQ*CH];            // 32 MB (tf32-rounded Q)
__device__ float g_Kb[BATCH*SEQ*CH];            // 32 MB (tf32-rounded K)
__device__ float g_Vt[BATCH*SEQ*CH];            // 32 MB (V^T per batch [CH, SEQ], rounded)
__device__ float g_S [(size_t)BATCH*SEQ*SEQ];   // 64 MB scores / probs
__device__ float g_At[BATCH*SEQ*CH];            // 32 MB attended
__device__ float g_XR[BATCH*SEQ*CH];            // 32 MB rounded x (later rounded residual)
__device__ float g_CR[BATCH*SEQ*CH];            // 32 MB rounded content_embeddings
__device__ float g_WR[4*CH*CH];                 // 16 MB rounded Wq,Wk,Wv,Wo

// ---------------- helpers ----------------
__device__ __forceinline__ uint32_t smem_u32(const void* p){
    uint32_t a;
    asm("{ .reg .u64 t; cvta.to.shared.u64 t, %1; cvt.u32.u64 %0, t; }" : "=r"(a) : "l"(p));
    return a;
}
__device__ __forceinline__ void cp16(uint32_t dst, const void* src){
    asm volatile("cp.async.cg.shared.global [%0], [%1], 16;" :: "r"(dst), "l"(src));
}
__device__ __forceinline__ float rn_tf32(float x){
    uint32_t u; asm("cvt.rna.tf32.f32 %0, %1;" : "=r"(u) : "f"(x));
    return __uint_as_float(u);
}
__device__ __forceinline__ void mma_tf32(float* d, const float* a, const float* b){
    asm volatile(
        "mma.sync.aligned.m16n8k8.row.col.f32.tf32.tf32.f32 "
        "{%0,%1,%2,%3}, {%4,%5,%6,%7}, {%8,%9}, {%0,%1,%2,%3};"
        : "+f"(d[0]), "+f"(d[1]), "+f"(d[2]), "+f"(d[3])
        : "r"(__float_as_uint(a[0])), "r"(__float_as_uint(a[1])),
          "r"(__float_as_uint(a[2])), "r"(__float_as_uint(a[3])),
          "r"(__float_as_uint(b[0])), "r"(__float_as_uint(b[1])));
}

// ---------------- tf32 tensor-core NT GEMM (mma.sync path, portable PTX) ----
// C[m,n] (+= bias[n]) = sum_k A[m,k]*B[n,k]; A:[M,K], B:[N,K] row-major.
// 128x128 tile, BK=32, 4-stage cp.async, 8 warps (2x4) at 64x32 warp tiles.
__global__ __launch_bounds__(256, 1) void gemm_tf32(
    const float* __restrict__ A, const float* __restrict__ Bm,
    const float* __restrict__ bias, float* __restrict__ Cm,
    int M, int N, int K,
    long long az, long long bz, long long cz, int round_out)
{
    extern __shared__ float sm[];
    float* As = sm;                       // [STAGES][BM][PAD]
    float* Bs = sm + STAGES * TILE_F;     // [STAGES][BN][PAD]
    const uint32_t asb = smem_u32(As);
    const uint32_t bsb = smem_u32(Bs);

    const int tid  = threadIdx.x;
    const int wid  = tid >> 5;
    const int lane = tid & 31;
    const int lq   = lane >> 2;   // 0..7
    const int lr   = lane & 3;    // 0..3

    const int z = blockIdx.z;
    const float* Ab = A  + (long long)z * az;
    const float* Bb = Bm + (long long)z * bz;
    float*       Cb = Cm + (long long)z * cz;
    const int m0 = blockIdx.y * BM;
    const int n0 = blockIdx.x * BN;
    const int KT = K / BK;

    const int warp_m = (wid & 1) * 64;    // 2 warps along M
    const int warp_n = (wid >> 1) * 32;   // 4 warps along N

    float acc[4][4][4];
    #pragma unroll
    for (int i = 0; i < 4; i++)
        #pragma unroll
        for (int j = 0; j < 4; j++)
            #pragma unroll
            for (int r = 0; r < 4; r++) acc[i][j][r] = 0.0f;

    // loader: tile is BM rows x 32 floats (128B = 8 chunks of 16B); 1024 chunks, 4/thread
    auto load_stage = [&](int slot, int kt) {
        const long long k0 = (long long)kt * BK;
        const uint32_t sa = asb + (uint32_t)slot * TILE_F * 4;
        const uint32_t sb2 = bsb + (uint32_t)slot * TILE_F * 4;
        #pragma unroll
        for (int it = 0; it < 4; it++) {
            int f = tid + it * 256;
            int row = f >> 3, c = f & 7;
            cp16(sa  + (uint32_t)(row * PAD * 4 + c * 16),
                 Ab + ((long long)(m0 + row) * K + k0 + c * 4));
        }
        #pragma unroll
        for (int it = 0; it < 4; it++) {
            int f = tid + it * 256;
            int row = f >> 3, c = f & 7;
            cp16(sb2 + (uint32_t)(row * PAD * 4 + c * 16),
                 Bb + ((long long)(n0 + row) * K + k0 + c * 4));
        }
        asm volatile("cp.async.commit_group;");
    };

    // prologue: preload STAGES-1 tiles
    #pragma unroll
    for (int s = 0; s < STAGES - 1; s++) {
        if (s < KT) load_stage(s, s);
        else asm volatile("cp.async.commit_group;");
    }

    for (int kt = 0; kt < KT; kt++) {
        asm volatile("cp.async.wait_group %0;" :: "n"(STAGES - 2));
        __syncthreads();

        const int slot = kt % STAGES;
        const float* Asl = As + slot * TILE_F;
        const float* Bsl = Bs + slot * TILE_F;

        #pragma unroll
        for (int ks = 0; ks < BK; ks += 8) {
            float af[4][4], bf[4][2];
            #pragma unroll
            for (int mf = 0; mf < 4; mf++) {
                const float* p = Asl + (warp_m + mf * 16 + lq) * PAD + ks + lr;
                af[mf][0] = p[0];
                af[mf][1] = p[8 * PAD];
                af[mf][2] = p[4];
                af[mf][3] = p[8 * PAD + 4];
            }
            #pragma unroll
            for (int nf = 0; nf < 4; nf++) {
                const float* p = Bsl + (warp_n + nf * 8 + lq) * PAD + ks + lr;
                bf[nf][0] = p[0];
                bf[nf][1] = p[4];
            }
            #pragma unroll
            for (int mf = 0; mf < 4; mf++)
                #pragma unroll
                for (int nf = 0; nf < 4; nf++)
                    mma_tf32(acc[mf][nf], af[mf], bf[nf]);
        }

        __syncthreads();
        const int nxt = kt + STAGES - 1;
        if (nxt < KT) load_stage(nxt % STAGES, nxt);
        else asm volatile("cp.async.commit_group;");
    }

    // -------- epilogue: regs -> gmem (float2 stores; sectors fully covered) ----
    #pragma unroll
    for (int mf = 0; mf < 4; mf++) {
        const int row = m0 + warp_m + mf * 16 + lq;
        #pragma unroll
        for (int nf = 0; nf < 4; nf++) {
            const int col = n0 + warp_n + nf * 8 + 2 * lr;
            float b0 = 0.f, b1 = 0.f;
            if (bias) { b0 = __ldg(&bias[col]); b1 = __ldg(&bias[col + 1]); }
            float v0 = acc[mf][nf][0] + b0, v1 = acc[mf][nf][1] + b1;
            float v2 = acc[mf][nf][2] + b0, v3 = acc[mf][nf][3] + b1;
            if (round_out) {
                v0 = rn_tf32(v0); v1 = rn_tf32(v1);
                v2 = rn_tf32(v2); v3 = rn_tf32(v3);
            }
            *reinterpret_cast<float2*>(&Cb[(long long)row * N + col])       = make_float2(v0, v1);
            *reinterpret_cast<float2*>(&Cb[(long long)(row + 8) * N + col]) = make_float2(v2, v3);
        }
    }
}

// ---------------- elementwise kernels ----------------
__global__ __launch_bounds__(256) void round_tf32_k(const float* __restrict__ a,
                                                    float* __restrict__ b, long long n4)
{
    long long i = ((long long)blockIdx.x * 256 + threadIdx.x);
    if (i >= n4) return;
    float4 v = reinterpret_cast<const float4*>(a)[i];
    v.x = rn_tf32(v.x); v.y = rn_tf32(v.y); v.z = rn_tf32(v.z); v.w = rn_tf32(v.w);
    reinterpret_cast<float4*>(b)[i] = v;
}

__global__ __launch_bounds__(256) void resid_round_k(const float* __restrict__ x,
                                                     const float* __restrict__ att,
                                                     float* __restrict__ r, long long n4)
{
    long long i = ((long long)blockIdx.x * 256 + threadIdx.x);
    if (i >= n4) return;
    float4 a = reinterpret_cast<const float4*>(x)[i];
    float4 b = reinterpret_cast<const float4*>(att)[i];
    a.x = rn_tf32(a.x + b.x); a.y = rn_tf32(a.y + b.y);
    a.z = rn_tf32(a.z + b.z); a.w = rn_tf32(a.w + b.w);
    reinterpret_cast<float4*>(r)[i] = a;
}

// row softmax of softmax(scale*s); output rounded to tf32 (feeds next MMA)
__global__ __launch_bounds__(256) void softmax_rows(float* __restrict__ S, int cols, float scale)
{
    float* p = S + (long long)blockIdx.x * cols;
    const int tid = threadIdx.x;
    __shared__ float red[256];

    float m = -1e30f;
    for (int i = tid; i < cols; i += 256) m = fmaxf(m, p[i]);
    red[tid] = m; __syncthreads();
    for (int s = 128; s > 0; s >>= 1) {
        if (tid < s) red[tid] = fmaxf(red[tid], red[tid + s]);
        __syncthreads();
    }
    m = red[0];
    __syncthreads();

    float sum = 0.0f;
    for (int i = tid; i < cols; i += 256) {
        float e = __expf((p[i] - m) * scale);
        p[i] = e;
        sum += e;
    }
    red[tid] = sum; __syncthreads();
    for (int s = 128; s > 0; s >>= 1) {
        if (tid < s) red[tid] += red[tid + s];
        __syncthreads();
    }
    float inv = 1.0f / red[0];
    for (int i = tid; i < cols; i += 256) p[i] = rn_tf32(p[i] * inv);
}

// ---------------- host launcher ----------------
extern "C" void kernel_launch(void* const* d_in, const int* in_sizes, int n_in,
                              void* d_out, int out_size)
{
    const float* x  = (const float*)d_in[0];
    const float* ce = (const float*)d_in[1];
    const float* Wq = (const float*)d_in[2];
    const float* bq = (const float*)d_in[3];
    const float* Wk = (const float*)d_in[4];
    const float* bk = (const float*)d_in[5];
    const float* Wv = (const float*)d_in[6];
    const float* bv = (const float*)d_in[7];
    const float* Wo = (const float*)d_in[8];
    const float* bo = (const float*)d_in[9];
    float* out = (float*)d_out;

    float *Q, *Kb, *Vt, *S, *At, *XR, *CR, *WR;
    cudaGetSymbolAddress((void**)&Q,  g_Q);
    cudaGetSymbolAddress((void**)&Kb, g_Kb);
    cudaGetSymbolAddress((void**)&Vt, g_Vt);
    cudaGetSymbolAddress((void**)&S,  g_S);
    cudaGetSymbolAddress((void**)&At, g_At);
    cudaGetSymbolAddress((void**)&XR, g_XR);
    cudaGetSymbolAddress((void**)&CR, g_CR);
    cudaGetSymbolAddress((void**)&WR, g_WR);
    float* WRq = WR + 0 * CH * CH;
    float* WRk = WR + 1 * CH * CH;
    float* WRv = WR + 2 * CH * CH;
    float* WRo = WR + 3 * CH * CH;

    const int SMEMB = STAGES * TILE_F * 4 * 2;   // 4*4608*4*2 = 147456 B
    cudaFuncSetAttribute(gemm_tf32, cudaFuncAttributeMaxDynamicSharedMemorySize, SMEMB);

    const long long NX4 = (long long)BATCH * SEQ * CH / 4;
    const long long NW4 = (long long)CH * CH / 4;
    dim3 t(256);

    // RN-round all MMA operand sources (zero-mean tf32 error)
    round_tf32_k<<<(unsigned)((NX4 + 255) / 256), t>>>(x,  XR, NX4);
    round_tf32_k<<<(unsigned)((NX4 + 255) / 256), t>>>(ce, CR, NX4);
    round_tf32_k<<<(unsigned)((NW4 + 255) / 256), t>>>(Wq, WRq, NW4);
    round_tf32_k<<<(unsigned)((NW4 + 255) / 256), t>>>(Wk, WRk, NW4);
    round_tf32_k<<<(unsigned)((NW4 + 255) / 256), t>>>(Wv, WRv, NW4);
    round_tf32_k<<<(unsigned)((NW4 + 255) / 256), t>>>(Wo, WRo, NW4);

    const int M = BATCH * SEQ;  // 8192

    // Q = x@Wq^T + bq (rounded);  K = ce@Wk^T + bk (rounded)
    gemm_tf32<<<dim3(CH / BN, M / BM, 1), t, SMEMB>>>(XR, WRq, bq, Q,  M, CH, CH, 0, 0, 0, 1);
    gemm_tf32<<<dim3(CH / BN, M / BM, 1), t, SMEMB>>>(CR, WRk, bk, Kb, M, CH, CH, 0, 0, 0, 1);

    // Vt_b[c, s] = sum_k Wv[c,k] * ce_b[s,k]  (rounded; no bias)
    gemm_tf32<<<dim3(SEQ / BN, CH / BM, BATCH), t, SMEMB>>>(
        WRv, CR, nullptr, Vt, CH, SEQ, CH,
        0, (long long)SEQ * CH, (long long)CH * SEQ, 1);

    // S_b = Q_b @ K_b^T (raw scores, fp32)
    gemm_tf32<<<dim3(SEQ / BN, SEQ / BM, BATCH), t, SMEMB>>>(
        Q, Kb, nullptr, S, SEQ, SEQ, CH,
        (long long)SEQ * CH, (long long)SEQ * CH, (long long)SEQ * SEQ, 0);

    // P = softmax(scale * S), rounded to tf32
    softmax_rows<<<BATCH * SEQ, t>>>(S, SEQ, 0.03125f);

    // At_b = P_b @ Vt_b^T + bv (rows of P sum to 1 -> bias fold is exact)
    gemm_tf32<<<dim3(CH / BN, SEQ / BM, BATCH), t, SMEMB>>>(
        S, Vt, bv, At, SEQ, CH, SEQ,
        (long long)SEQ * SEQ, (long long)CH * SEQ, (long long)SEQ * CH, 0);

    // residual: XR = rn_tf32(x + At)
    resid_round_k<<<(unsigned)((NX4 + 255) / 256), t>>>(x, At, XR, NX4);

    // out = (x+At) @ Wo^T + bo (full fp32 output)
    gemm_tf32<<<dim3(CH / BN, M / BM, 1), t, SMEMB>>>(XR, WRo, bo, out, M, CH, CH, 0, 0, 0, 0);
}

// round 6
// speedup vs baseline: 3.6114x; 1.1466x over previous
#include <cuda_runtime.h>
#include <cstdint>

#define BATCH 4
#define SEQ   2048
#define CH    1024

#define BM 128
#define BN 256
#define BK 32
#define STAGES 3
#define PAD 36              // floats per smem row (32 data + 4 pad) -> conflict-free frags
#define ASZ_F (BM * PAD)    // 4608 floats per A stage
#define BSZ_F (BN * PAD)    // 9216 floats per B stage

// ---------------- scratch (device globals; allocation-free) ----------------
__device__ float g_Q [BATCH*SEQ*CH];            // 32 MB (tf32-rounded Q)
__device__ float g_Kb[BATCH*SEQ*CH];            // 32 MB (tf32-rounded K)
__device__ float g_Vt[BATCH*SEQ*CH];            // 32 MB (V^T per batch [CH, SEQ], rounded)
__device__ float g_S [(size_t)BATCH*SEQ*SEQ];   // 64 MB scores / probs
__device__ float g_At[BATCH*SEQ*CH];            // 32 MB attended
__device__ float g_XR[BATCH*SEQ*CH];            // 32 MB rounded x (later rounded residual)
__device__ float g_CR[BATCH*SEQ*CH];            // 32 MB rounded content_embeddings
__device__ float g_WR[4*CH*CH];                 // 16 MB rounded Wq,Wk,Wv,Wo

// ---------------- helpers ----------------
__device__ __forceinline__ uint32_t smem_u32(const void* p){
    uint32_t a;
    asm("{ .reg .u64 t; cvta.to.shared.u64 t, %1; cvt.u32.u64 %0, t; }" : "=r"(a) : "l"(p));
    return a;
}
__device__ __forceinline__ void cp16(uint32_t dst, const void* src){
    asm volatile("cp.async.cg.shared.global [%0], [%1], 16;" :: "r"(dst), "l"(src));
}
__device__ __forceinline__ float rn_tf32(float x){
    uint32_t u; asm("cvt.rna.tf32.f32 %0, %1;" : "=r"(u) : "f"(x));
    return __uint_as_float(u);
}
__device__ __forceinline__ void mma_tf32(float* d, const float* a, const float* b){
    asm volatile(
        "mma.sync.aligned.m16n8k8.row.col.f32.tf32.tf32.f32 "
        "{%0,%1,%2,%3}, {%4,%5,%6,%7}, {%8,%9}, {%0,%1,%2,%3};"
        : "+f"(d[0]), "+f"(d[1]), "+f"(d[2]), "+f"(d[3])
        : "r"(__float_as_uint(a[0])), "r"(__float_as_uint(a[1])),
          "r"(__float_as_uint(a[2])), "r"(__float_as_uint(a[3])),
          "r"(__float_as_uint(b[0])), "r"(__float_as_uint(b[1])));
}

// ---------------- tf32 tensor-core NT GEMM ----------------
// C[m,n] (+= bias[n]) = sum_k A[m,k]*B[n,k]; A:[M,K], B:[N,K] row-major.
// 128x256 block tile, 64x64 warp tiles (8 warps, 2x4), BK=32, 3-stage cp.async.
__global__ __launch_bounds__(256, 1) void gemm_tf32(
    const float* __restrict__ A, const float* __restrict__ Bm,
    const float* __restrict__ bias, float* __restrict__ Cm,
    int M, int N, int K,
    long long az, long long bz, long long cz, int round_out)
{
    extern __shared__ float sm[];
    float* As = sm;                         // [STAGES][BM][PAD]
    float* Bs = sm + STAGES * ASZ_F;        // [STAGES][BN][PAD]
    const uint32_t asb = smem_u32(As);
    const uint32_t bsb = smem_u32(Bs);

    const int tid  = threadIdx.x;
    const int wid  = tid >> 5;
    const int lane = tid & 31;
    const int lq   = lane >> 2;   // 0..7
    const int lr   = lane & 3;    // 0..3

    const int z = blockIdx.z;
    const float* Ab = A  + (long long)z * az;
    const float* Bb = Bm + (long long)z * bz;
    float*       Cb = Cm + (long long)z * cz;
    const int m0 = blockIdx.y * BM;
    const int n0 = blockIdx.x * BN;
    const int KT = K / BK;

    const int warp_m = (wid & 1) * 64;    // 2 warps along M
    const int warp_n = (wid >> 1) * 64;   // 4 warps along N

    float acc[4][8][4];
    #pragma unroll
    for (int i = 0; i < 4; i++)
        #pragma unroll
        for (int j = 0; j < 8; j++)
            #pragma unroll
            for (int r = 0; r < 4; r++) acc[i][j][r] = 0.0f;

    // loader: A = 1024 16B-chunks (4/thread), B = 2048 chunks (8/thread)
    auto load_stage = [&](int slot, int kt) {
        const long long k0 = (long long)kt * BK;
        const uint32_t sa  = asb + (uint32_t)slot * ASZ_F * 4;
        const uint32_t sb2 = bsb + (uint32_t)slot * BSZ_F * 4;
        #pragma unroll
        for (int it = 0; it < 4; it++) {
            int f = tid + it * 256;
            int row = f >> 3, c = f & 7;
            cp16(sa  + (uint32_t)(row * PAD * 4 + c * 16),
                 Ab + ((long long)(m0 + row) * K + k0 + c * 4));
        }
        #pragma unroll
        for (int it = 0; it < 8; it++) {
            int f = tid + it * 256;
            int row = f >> 3, c = f & 7;
            cp16(sb2 + (uint32_t)(row * PAD * 4 + c * 16),
                 Bb + ((long long)(n0 + row) * K + k0 + c * 4));
        }
        asm volatile("cp.async.commit_group;");
    };

    // prologue: preload STAGES-1 tiles
    #pragma unroll
    for (int s = 0; s < STAGES - 1; s++) {
        if (s < KT) load_stage(s, s);
        else asm volatile("cp.async.commit_group;");
    }

    for (int kt = 0; kt < KT; kt++) {
        asm volatile("cp.async.wait_group %0;" :: "n"(STAGES - 2));
        __syncthreads();

        const int slot = kt % STAGES;
        const float* Asl = As + slot * ASZ_F;
        const float* Bsl = Bs + slot * BSZ_F;

        #pragma unroll
        for (int ks = 0; ks < BK; ks += 8) {
            float af[4][4], bf[8][2];
            #pragma unroll
            for (int mf = 0; mf < 4; mf++) {
                const float* p = Asl + (warp_m + mf * 16 + lq) * PAD + ks + lr;
                af[mf][0] = p[0];
                af[mf][1] = p[8 * PAD];
                af[mf][2] = p[4];
                af[mf][3] = p[8 * PAD + 4];
            }
            #pragma unroll
            for (int nf = 0; nf < 8; nf++) {
                const float* p = Bsl + (warp_n + nf * 8 + lq) * PAD + ks + lr;
                bf[nf][0] = p[0];
                bf[nf][1] = p[4];
            }
            #pragma unroll
            for (int mf = 0; mf < 4; mf++)
                #pragma unroll
                for (int nf = 0; nf < 8; nf++)
                    mma_tf32(acc[mf][nf], af[mf], bf[nf]);
        }

        __syncthreads();
        const int nxt = kt + STAGES - 1;
        if (nxt < KT) load_stage(nxt % STAGES, nxt);
        else asm volatile("cp.async.commit_group;");
    }

    // -------- epilogue: regs -> gmem (float2 stores; sectors fully covered) ----
    #pragma unroll
    for (int mf = 0; mf < 4; mf++) {
        const int row = m0 + warp_m + mf * 16 + lq;
        #pragma unroll
        for (int nf = 0; nf < 8; nf++) {
            const int col = n0 + warp_n + nf * 8 + 2 * lr;
            float b0 = 0.f, b1 = 0.f;
            if (bias) { b0 = __ldg(&bias[col]); b1 = __ldg(&bias[col + 1]); }
            float v0 = acc[mf][nf][0] + b0, v1 = acc[mf][nf][1] + b1;
            float v2 = acc[mf][nf][2] + b0, v3 = acc[mf][nf][3] + b1;
            if (round_out) {
                v0 = rn_tf32(v0); v1 = rn_tf32(v1);
                v2 = rn_tf32(v2); v3 = rn_tf32(v3);
            }
            *reinterpret_cast<float2*>(&Cb[(long long)row * N + col])       = make_float2(v0, v1);
            *reinterpret_cast<float2*>(&Cb[(long long)(row + 8) * N + col]) = make_float2(v2, v3);
        }
    }
}

// ---------------- elementwise kernels ----------------
__global__ __launch_bounds__(256) void round_tf32_k(const float* __restrict__ a,
                                                    float* __restrict__ b, long long n4)
{
    long long i = ((long long)blockIdx.x * 256 + threadIdx.x);
    if (i >= n4) return;
    float4 v = reinterpret_cast<const float4*>(a)[i];
    v.x = rn_tf32(v.x); v.y = rn_tf32(v.y); v.z = rn_tf32(v.z); v.w = rn_tf32(v.w);
    reinterpret_cast<float4*>(b)[i] = v;
}

// round 4 weight matrices in one launch (blockIdx.y selects matrix)
__global__ __launch_bounds__(256) void round_w4_k(
    const float* __restrict__ w0, const float* __restrict__ w1,
    const float* __restrict__ w2, const float* __restrict__ w3,
    float* __restrict__ dst, long long n4)
{
    const float* srcs[4] = {w0, w1, w2, w3};
    const float* a = srcs[blockIdx.y];
    float* b = dst + (long long)blockIdx.y * (n4 * 4);
    long long i = ((long long)blockIdx.x * 256 + threadIdx.x);
    if (i >= n4) return;
    float4 v = reinterpret_cast<const float4*>(a)[i];
    v.x = rn_tf32(v.x); v.y = rn_tf32(v.y); v.z = rn_tf32(v.z); v.w = rn_tf32(v.w);
    reinterpret_cast<float4*>(b)[i] = v;
}

__global__ __launch_bounds__(256) void resid_round_k(const float* __restrict__ x,
                                                     const float* __restrict__ att,
                                                     float* __restrict__ r, long long n4)
{
    long long i = ((long long)blockIdx.x * 256 + threadIdx.x);
    if (i >= n4) return;
    float4 a = reinterpret_cast<const float4*>(x)[i];
    float4 b = reinterpret_cast<const float4*>(att)[i];
    a.x = rn_tf32(a.x + b.x); a.y = rn_tf32(a.y + b.y);
    a.z = rn_tf32(a.z + b.z); a.w = rn_tf32(a.w + b.w);
    reinterpret_cast<float4*>(r)[i] = a;
}

// single-pass register-resident softmax for rows of exactly 2048 cols.
// out = rn_tf32(softmax(scale * s)); one global read + one global write.
__global__ __launch_bounds__(256) void softmax2048(float* __restrict__ S, float scale)
{
    float* p = S + (long long)blockIdx.x * 2048;
    const int tid  = threadIdx.x;
    const int lane = tid & 31, wrp = tid >> 5;
    __shared__ float red[8];

    float4 v0 = *reinterpret_cast<const float4*>(p + tid * 4);
    float4 v1 = *reinterpret_cast<const float4*>(p + 1024 + tid * 4);

    float m = fmaxf(fmaxf(fmaxf(v0.x, v0.y), fmaxf(v0.z, v0.w)),
                    fmaxf(fmaxf(v1.x, v1.y), fmaxf(v1.z, v1.w)));
    #pragma unroll
    for (int o = 16; o > 0; o >>= 1) m = fmaxf(m, __shfl_xor_sync(0xffffffffu, m, o));
    if (lane == 0) red[wrp] = m;
    __syncthreads();
    m = red[lane & 7];
    #pragma unroll
    for (int o = 4; o > 0; o >>= 1) m = fmaxf(m, __shfl_xor_sync(0xffffffffu, m, o));

    v0.x = __expf((v0.x - m) * scale); v0.y = __expf((v0.y - m) * scale);
    v0.z = __expf((v0.z - m) * scale); v0.w = __expf((v0.w - m) * scale);
    v1.x = __expf((v1.x - m) * scale); v1.y = __expf((v1.y - m) * scale);
    v1.z = __expf((v1.z - m) * scale); v1.w = __expf((v1.w - m) * scale);

    float s = (v0.x + v0.y) + (v0.z + v0.w) + (v1.x + v1.y) + (v1.z + v1.w);
    #pragma unroll
    for (int o = 16; o > 0; o >>= 1) s += __shfl_xor_sync(0xffffffffu, s, o);
    __syncthreads();
    if (lane == 0) red[wrp] = s;
    __syncthreads();
    s = red[lane & 7];
    #pragma unroll
    for (int o = 4; o > 0; o >>= 1) s += __shfl_xor_sync(0xffffffffu, s, o);

    const float inv = 1.0f / s;
    v0.x = rn_tf32(v0.x * inv); v0.y = rn_tf32(v0.y * inv);
    v0.z = rn_tf32(v0.z * inv); v0.w = rn_tf32(v0.w * inv);
    v1.x = rn_tf32(v1.x * inv); v1.y = rn_tf32(v1.y * inv);
    v1.z = rn_tf32(v1.z * inv); v1.w = rn_tf32(v1.w * inv);
    *reinterpret_cast<float4*>(p + tid * 4) = v0;
    *reinterpret_cast<float4*>(p + 1024 + tid * 4) = v1;
}

// ---------------- host launcher ----------------
extern "C" void kernel_launch(void* const* d_in, const int* in_sizes, int n_in,
                              void* d_out, int out_size)
{
    const float* x  = (const float*)d_in[0];
    const float* ce = (const float*)d_in[1];
    const float* Wq = (const float*)d_in[2];
    const float* bq = (const float*)d_in[3];
    const float* Wk = (const float*)d_in[4];
    const float* bk = (const float*)d_in[5];
    const float* Wv = (const float*)d_in[6];
    const float* bv = (const float*)d_in[7];
    const float* Wo = (const float*)d_in[8];
    const float* bo = (const float*)d_in[9];
    float* out = (float*)d_out;

    float *Q, *Kb, *Vt, *S, *At, *XR, *CR, *WR;
    cudaGetSymbolAddress((void**)&Q,  g_Q);
    cudaGetSymbolAddress((void**)&Kb, g_Kb);
    cudaGetSymbolAddress((void**)&Vt, g_Vt);
    cudaGetSymbolAddress((void**)&S,  g_S);
    cudaGetSymbolAddress((void**)&At, g_At);
    cudaGetSymbolAddress((void**)&XR, g_XR);
    cudaGetSymbolAddress((void**)&CR, g_CR);
    cudaGetSymbolAddress((void**)&WR, g_WR);
    float* WRq = WR + 0 * CH * CH;
    float* WRk = WR + 1 * CH * CH;
    float* WRv = WR + 2 * CH * CH;
    float* WRo = WR + 3 * CH * CH;

    const int SMEMB = STAGES * (ASZ_F + BSZ_F) * 4;   // 3*13824*4 = 165888 B
    cudaFuncSetAttribute(gemm_tf32, cudaFuncAttributeMaxDynamicSharedMemorySize, SMEMB);

    const long long NX4 = (long long)BATCH * SEQ * CH / 4;
    const long long NW4 = (long long)CH * CH / 4;
    dim3 t(256);

    // RN-round all MMA operand sources (zero-mean tf32 error)
    round_tf32_k<<<(unsigned)((NX4 + 255) / 256), t>>>(x,  XR, NX4);
    round_tf32_k<<<(unsigned)((NX4 + 255) / 256), t>>>(ce, CR, NX4);
    round_w4_k<<<dim3((unsigned)((NW4 + 255) / 256), 4), t>>>(Wq, Wk, Wv, Wo, WR, NW4);

    const int M = BATCH * SEQ;  // 8192

    // Q = x@Wq^T + bq (rounded);  K = ce@Wk^T + bk (rounded)
    gemm_tf32<<<dim3(CH / BN, M / BM, 1), t, SMEMB>>>(XR, WRq, bq, Q,  M, CH, CH, 0, 0, 0, 1);
    gemm_tf32<<<dim3(CH / BN, M / BM, 1), t, SMEMB>>>(CR, WRk, bk, Kb, M, CH, CH, 0, 0, 0, 1);

    // Vt_b[c, s] = sum_k Wv[c,k] * ce_b[s,k]  (rounded; no bias)
    gemm_tf32<<<dim3(SEQ / BN, CH / BM, BATCH), t, SMEMB>>>(
        WRv, CR, nullptr, Vt, CH, SEQ, CH,
        0, (long long)SEQ * CH, (long long)CH * SEQ, 1);

    // S_b = Q_b @ K_b^T (raw scores, fp32)
    gemm_tf32<<<dim3(SEQ / BN, SEQ / BM, BATCH), t, SMEMB>>>(
        Q, Kb, nullptr, S, SEQ, SEQ, CH,
        (long long)SEQ * CH, (long long)SEQ * CH, (long long)SEQ * SEQ, 0);

    // P = rn_tf32(softmax(scale * S)) — single pass, register resident
    softmax2048<<<BATCH * SEQ, t>>>(S, 0.03125f);

    // At_b = P_b @ Vt_b^T + bv (rows of P sum to 1 -> bias fold is exact)
    gemm_tf32<<<dim3(CH / BN, SEQ / BM, BATCH), t, SMEMB>>>(
        S, Vt, bv, At, SEQ, CH, SEQ,
        (long long)SEQ * SEQ, (long long)CH * SEQ, (long long)SEQ * CH, 0);

    // residual: XR = rn_tf32(x + At)
    resid_round_k<<<(unsigned)((NX4 + 255) / 256), t>>>(x, At, XR, NX4);

    // out = (x+At) @ Wo^T + bo (full fp32 output)
    gemm_tf32<<<dim3(CH / BN, M / BM, 1), t, SMEMB>>>(XR, WRo, bo, out, M, CH, CH, 0, 0, 0, 0);
}

// round 7
// speedup vs baseline: 3.8327x; 1.0613x over previous
#include <cuda_runtime.h>
#include <cstdint>

#define BATCH 4
#define SEQ   2048
#define CH    1024

#define BM 128
#define BN 256
#define BK 32
#define STAGES 3
#define PAD 40              // floats per smem row (32 data + 8 pad) -> conflict-free float2 frags
#define ASZ_F (BM * PAD)    // 5120 floats per A stage
#define BSZ_F (BN * PAD)    // 10240 floats per B stage

// ---------------- scratch (device globals; allocation-free) ----------------
__device__ float g_Q [BATCH*SEQ*CH];            // 32 MB (tf32-rounded Q)
__device__ float g_Kb[BATCH*SEQ*CH];            // 32 MB (tf32-rounded K)
__device__ float g_Vt[BATCH*SEQ*CH];            // 32 MB (V^T per batch [CH, SEQ], rounded)
__device__ float g_S [(size_t)BATCH*SEQ*SEQ];   // 64 MB scores / probs
__device__ float g_At[BATCH*SEQ*CH];            // 32 MB attended
__device__ float g_XR[BATCH*SEQ*CH];            // 32 MB rounded x (later rounded residual)
__device__ float g_CR[BATCH*SEQ*CH];            // 32 MB rounded content_embeddings
__device__ float g_WR[4*CH*CH];                 // 16 MB rounded Wq,Wk,Wv,Wo

// ---------------- helpers ----------------
__device__ __forceinline__ uint32_t smem_u32(const void* p){
    uint32_t a;
    asm("{ .reg .u64 t; cvta.to.shared.u64 t, %1; cvt.u32.u64 %0, t; }" : "=r"(a) : "l"(p));
    return a;
}
__device__ __forceinline__ void cp16(uint32_t dst, const void* src){
    asm volatile("cp.async.cg.shared.global [%0], [%1], 16;" :: "r"(dst), "l"(src));
}
__device__ __forceinline__ float rn_tf32(float x){
    uint32_t u; asm("cvt.rna.tf32.f32 %0, %1;" : "=r"(u) : "f"(x));
    return __uint_as_float(u);
}
__device__ __forceinline__ void mma_tf32(float* d, const float* a, const float* b){
    asm volatile(
        "mma.sync.aligned.m16n8k8.row.col.f32.tf32.tf32.f32 "
        "{%0,%1,%2,%3}, {%4,%5,%6,%7}, {%8,%9}, {%0,%1,%2,%3};"
        : "+f"(d[0]), "+f"(d[1]), "+f"(d[2]), "+f"(d[3])
        : "r"(__float_as_uint(a[0])), "r"(__float_as_uint(a[1])),
          "r"(__float_as_uint(a[2])), "r"(__float_as_uint(a[3])),
          "r"(__float_as_uint(b[0])), "r"(__float_as_uint(b[1])));
}

// ---------------- tf32 tensor-core NT GEMM ----------------
// C[m,n] (+= bias[n]) = sum_k A[m,k]*B[n,k]; A:[M,K], B:[N,K] row-major.
// 128x256 block tile, 64x64 warp tiles (8 warps, 2x4), BK=32, 3-stage cp.async.
// Fragment k-slots are permuted (slot lr <-> k=2lr, slot lr+4 <-> k=2lr+1) so
// each thread's two k-values are adjacent -> one LDS.64 per fragment pair.
// Contraction is order-invariant within the 8-k group, so results are identical.
__global__ __launch_bounds__(256, 1) void gemm_tf32(
    const float* __restrict__ A, const float* __restrict__ Bm,
    const float* __restrict__ bias, float* __restrict__ Cm,
    int M, int N, int K,
    long long az, long long bz, long long cz, int round_out)
{
    extern __shared__ float sm[];
    float* As = sm;                         // [STAGES][BM][PAD]
    float* Bs = sm + STAGES * ASZ_F;        // [STAGES][BN][PAD]
    const uint32_t asb = smem_u32(As);
    const uint32_t bsb = smem_u32(Bs);

    const int tid  = threadIdx.x;
    const int wid  = tid >> 5;
    const int lane = tid & 31;
    const int lq   = lane >> 2;   // 0..7
    const int lr   = lane & 3;    // 0..3

    const int z = blockIdx.z;
    const float* Ab = A  + (long long)z * az;
    const float* Bb = Bm + (long long)z * bz;
    float*       Cb = Cm + (long long)z * cz;
    const int m0 = blockIdx.y * BM;
    const int n0 = blockIdx.x * BN;
    const int KT = K / BK;

    const int warp_m = (wid & 1) * 64;    // 2 warps along M
    const int warp_n = (wid >> 1) * 64;   // 4 warps along N

    float acc[4][8][4];
    #pragma unroll
    for (int i = 0; i < 4; i++)
        #pragma unroll
        for (int j = 0; j < 8; j++)
            #pragma unroll
            for (int r = 0; r < 4; r++) acc[i][j][r] = 0.0f;

    // loader: A = 1024 16B-chunks (4/thread), B = 2048 chunks (8/thread)
    auto load_stage = [&](int slot, int kt) {
        const long long k0 = (long long)kt * BK;
        const uint32_t sa  = asb + (uint32_t)slot * ASZ_F * 4;
        const uint32_t sb2 = bsb + (uint32_t)slot * BSZ_F * 4;
        #pragma unroll
        for (int it = 0; it < 4; it++) {
            int f = tid + it * 256;
            int row = f >> 3, c = f & 7;
            cp16(sa  + (uint32_t)(row * PAD * 4 + c * 16),
                 Ab + ((long long)(m0 + row) * K + k0 + c * 4));
        }
        #pragma unroll
        for (int it = 0; it < 8; it++) {
            int f = tid + it * 256;
            int row = f >> 3, c = f & 7;
            cp16(sb2 + (uint32_t)(row * PAD * 4 + c * 16),
                 Bb + ((long long)(n0 + row) * K + k0 + c * 4));
        }
        asm volatile("cp.async.commit_group;");
    };

    // prologue: preload STAGES-1 tiles
    #pragma unroll
    for (int s = 0; s < STAGES - 1; s++) {
        if (s < KT) load_stage(s, s);
        else asm volatile("cp.async.commit_group;");
    }

    for (int kt = 0; kt < KT; kt++) {
        asm volatile("cp.async.wait_group %0;" :: "n"(STAGES - 2));
        __syncthreads();

        // issue next stage's loads first (slot was fully consumed last iter)
        const int nxt = kt + STAGES - 1;
        if (nxt < KT) load_stage(nxt % STAGES, nxt);
        else asm volatile("cp.async.commit_group;");

        const int slot = kt % STAGES;
        const float* Asl = As + slot * ASZ_F;
        const float* Bsl = Bs + slot * BSZ_F;

        #pragma unroll
        for (int ks = 0; ks < BK; ks += 8) {
            float af[4][4], bf[8][2];
            #pragma unroll
            for (int mf = 0; mf < 4; mf++) {
                const float* pa = Asl + (warp_m + mf * 16 + lq) * PAD + ks + 2 * lr;
                float2 lo = *reinterpret_cast<const float2*>(pa);
                float2 hi = *reinterpret_cast<const float2*>(pa + 8 * PAD);
                af[mf][0] = lo.x; af[mf][2] = lo.y;   // slots lr, lr+4 (rows lq)
                af[mf][1] = hi.x; af[mf][3] = hi.y;   // rows lq+8
            }
            #pragma unroll
            for (int nf = 0; nf < 8; nf++) {
                float2 v = *reinterpret_cast<const float2*>(
                    Bsl + (warp_n + nf * 8 + lq) * PAD + ks + 2 * lr);
                bf[nf][0] = v.x; bf[nf][1] = v.y;     // slots lr, lr+4
            }
            #pragma unroll
            for (int mf = 0; mf < 4; mf++)
                #pragma unroll
                for (int nf = 0; nf < 8; nf++)
                    mma_tf32(acc[mf][nf], af[mf], bf[nf]);
        }
        __syncthreads();
    }

    // -------- epilogue: regs -> gmem (float2 stores; sectors fully covered) ----
    #pragma unroll
    for (int mf = 0; mf < 4; mf++) {
        const int row = m0 + warp_m + mf * 16 + lq;
        #pragma unroll
        for (int nf = 0; nf < 8; nf++) {
            const int col = n0 + warp_n + nf * 8 + 2 * lr;
            float b0 = 0.f, b1 = 0.f;
            if (bias) { b0 = __ldg(&bias[col]); b1 = __ldg(&bias[col + 1]); }
            float v0 = acc[mf][nf][0] + b0, v1 = acc[mf][nf][1] + b1;
            float v2 = acc[mf][nf][2] + b0, v3 = acc[mf][nf][3] + b1;
            if (round_out) {
                v0 = rn_tf32(v0); v1 = rn_tf32(v1);
                v2 = rn_tf32(v2); v3 = rn_tf32(v3);
            }
            *reinterpret_cast<float2*>(&Cb[(long long)row * N + col])       = make_float2(v0, v1);
            *reinterpret_cast<float2*>(&Cb[(long long)(row + 8) * N + col]) = make_float2(v2, v3);
        }
    }
}

// ---------------- elementwise kernels ----------------
__global__ __launch_bounds__(256) void round_tf32_k(const float* __restrict__ a,
                                                    float* __restrict__ b, long long n4)
{
    long long i = ((long long)blockIdx.x * 256 + threadIdx.x);
    if (i >= n4) return;
    float4 v = reinterpret_cast<const float4*>(a)[i];
    v.x = rn_tf32(v.x); v.y = rn_tf32(v.y); v.z = rn_tf32(v.z); v.w = rn_tf32(v.w);
    reinterpret_cast<float4*>(b)[i] = v;
}

// round 4 weight matrices in one launch (blockIdx.y selects matrix)
__global__ __launch_bounds__(256) void round_w4_k(
    const float* __restrict__ w0, const float* __restrict__ w1,
    const float* __restrict__ w2, const float* __restrict__ w3,
    float* __restrict__ dst, long long n4)
{
    const float* srcs[4] = {w0, w1, w2, w3};
    const float* a = srcs[blockIdx.y];
    float* b = dst + (long long)blockIdx.y * (n4 * 4);
    long long i = ((long long)blockIdx.x * 256 + threadIdx.x);
    if (i >= n4) return;
    float4 v = reinterpret_cast<const float4*>(a)[i];
    v.x = rn_tf32(v.x); v.y = rn_tf32(v.y); v.z = rn_tf32(v.z); v.w = rn_tf32(v.w);
    reinterpret_cast<float4*>(b)[i] = v;
}

__global__ __launch_bounds__(256) void resid_round_k(const float* __restrict__ x,
                                                     const float* __restrict__ att,
                                                     float* __restrict__ r, long long n4)
{
    long long i = ((long long)blockIdx.x * 256 + threadIdx.x);
    if (i >= n4) return;
    float4 a = reinterpret_cast<const float4*>(x)[i];
    float4 b = reinterpret_cast<const float4*>(att)[i];
    a.x = rn_tf32(a.x + b.x); a.y = rn_tf32(a.y + b.y);
    a.z = rn_tf32(a.z + b.z); a.w = rn_tf32(a.w + b.w);
    reinterpret_cast<float4*>(r)[i] = a;
}

// single-pass register-resident softmax for rows of exactly 2048 cols.
// out = rn_tf32(softmax(scale * s)); one global read + one global write.
__global__ __launch_bounds__(256) void softmax2048(float* __restrict__ S, float scale)
{
    float* p = S + (long long)blockIdx.x * 2048;
    const int tid  = threadIdx.x;
    const int lane = tid & 31, wrp = tid >> 5;
    __shared__ float red[8];

    float4 v0 = *reinterpret_cast<const float4*>(p + tid * 4);
    float4 v1 = *reinterpret_cast<const float4*>(p + 1024 + tid * 4);

    float m = fmaxf(fmaxf(fmaxf(v0.x, v0.y), fmaxf(v0.z, v0.w)),
                    fmaxf(fmaxf(v1.x, v1.y), fmaxf(v1.z, v1.w)));
    #pragma unroll
    for (int o = 16; o > 0; o >>= 1) m = fmaxf(m, __shfl_xor_sync(0xffffffffu, m, o));
    if (lane == 0) red[wrp] = m;
    __syncthreads();
    m = red[lane & 7];
    #pragma unroll
    for (int o = 4; o > 0; o >>= 1) m = fmaxf(m, __shfl_xor_sync(0xffffffffu, m, o));

    v0.x = __expf((v0.x - m) * scale); v0.y = __expf((v0.y - m) * scale);
    v0.z = __expf((v0.z - m) * scale); v0.w = __expf((v0.w - m) * scale);
    v1.x = __expf((v1.x - m) * scale); v1.y = __expf((v1.y - m) * scale);
    v1.z = __expf((v1.z - m) * scale); v1.w = __expf((v1.w - m) * scale);

    float s = (v0.x + v0.y) + (v0.z + v0.w) + (v1.x + v1.y) + (v1.z + v1.w);
    #pragma unroll
    for (int o = 16; o > 0; o >>= 1) s += __shfl_xor_sync(0xffffffffu, s, o);
    __syncthreads();
    if (lane == 0) red[wrp] = s;
    __syncthreads();
    s = red[lane & 7];
    #pragma unroll
    for (int o = 4; o > 0; o >>= 1) s += __shfl_xor_sync(0xffffffffu, s, o);

    const float inv = 1.0f / s;
    v0.x = rn_tf32(v0.x * inv); v0.y = rn_tf32(v0.y * inv);
    v0.z = rn_tf32(v0.z * inv); v0.w = rn_tf32(v0.w * inv);
    v1.x = rn_tf32(v1.x * inv); v1.y = rn_tf32(v1.y * inv);
    v1.z = rn_tf32(v1.z * inv); v1.w = rn_tf32(v1.w * inv);
    *reinterpret_cast<float4*>(p + tid * 4) = v0;
    *reinterpret_cast<float4*>(p + 1024 + tid * 4) = v1;
}

// ---------------- host launcher ----------------
extern "C" void kernel_launch(void* const* d_in, const int* in_sizes, int n_in,
                              void* d_out, int out_size)
{
    const float* x  = (const float*)d_in[0];
    const float* ce = (const float*)d_in[1];
    const float* Wq = (const float*)d_in[2];
    const float* bq = (const float*)d_in[3];
    const float* Wk = (const float*)d_in[4];
    const float* bk = (const float*)d_in[5];
    const float* Wv = (const float*)d_in[6];
    const float* bv = (const float*)d_in[7];
    const float* Wo = (const float*)d_in[8];
    const float* bo = (const float*)d_in[9];
    float* out = (float*)d_out;

    float *Q, *Kb, *Vt, *S, *At, *XR, *CR, *WR;
    cudaGetSymbolAddress((void**)&Q,  g_Q);
    cudaGetSymbolAddress((void**)&Kb, g_Kb);
    cudaGetSymbolAddress((void**)&Vt, g_Vt);
    cudaGetSymbolAddress((void**)&S,  g_S);
    cudaGetSymbolAddress((void**)&At, g_At);
    cudaGetSymbolAddress((void**)&XR, g_XR);
    cudaGetSymbolAddress((void**)&CR, g_CR);
    cudaGetSymbolAddress((void**)&WR, g_WR);
    float* WRq = WR + 0 * CH * CH;
    float* WRk = WR + 1 * CH * CH;
    float* WRv = WR + 2 * CH * CH;
    float* WRo = WR + 3 * CH * CH;

    const int SMEMB = STAGES * (ASZ_F + BSZ_F) * 4;   // 3*15360*4 = 184320 B
    cudaFuncSetAttribute(gemm_tf32, cudaFuncAttributeMaxDynamicSharedMemorySize, SMEMB);

    const long long NX4 = (long long)BATCH * SEQ * CH / 4;
    const long long NW4 = (long long)CH * CH / 4;
    dim3 t(256);

    // RN-round all MMA operand sources (zero-mean tf32 error)
    round_tf32_k<<<(unsigned)((NX4 + 255) / 256), t>>>(x,  XR, NX4);
    round_tf32_k<<<(unsigned)((NX4 + 255) / 256), t>>>(ce, CR, NX4);
    round_w4_k<<<dim3((unsigned)((NW4 + 255) / 256), 4), t>>>(Wq, Wk, Wv, Wo, WR, NW4);

    const int M = BATCH * SEQ;  // 8192

    // Q = x@Wq^T + bq (rounded);  K = ce@Wk^T + bk (rounded)
    gemm_tf32<<<dim3(CH / BN, M / BM, 1), t, SMEMB>>>(XR, WRq, bq, Q,  M, CH, CH, 0, 0, 0, 1);
    gemm_tf32<<<dim3(CH / BN, M / BM, 1), t, SMEMB>>>(CR, WRk, bk, Kb, M, CH, CH, 0, 0, 0, 1);

    // Vt_b[c, s] = sum_k Wv[c,k] * ce_b[s,k]  (rounded; no bias)
    gemm_tf32<<<dim3(SEQ / BN, CH / BM, BATCH), t, SMEMB>>>(
        WRv, CR, nullptr, Vt, CH, SEQ, CH,
        0, (long long)SEQ * CH, (long long)CH * SEQ, 1);

    // S_b = Q_b @ K_b^T (raw scores, fp32)
    gemm_tf32<<<dim3(SEQ / BN, SEQ / BM, BATCH), t, SMEMB>>>(
        Q, Kb, nullptr, S, SEQ, SEQ, CH,
        (long long)SEQ * CH, (long long)SEQ * CH, (long long)SEQ * SEQ, 0);

    // P = rn_tf32(softmax(scale * S)) — single pass, register resident
    softmax2048<<<BATCH * SEQ, t>>>(S, 0.03125f);

    // At_b = P_b @ Vt_b^T + bv (rows of P sum to 1 -> bias fold is exact)
    gemm_tf32<<<dim3(CH / BN, SEQ / BM, BATCH), t, SMEMB>>>(
        S, Vt, bv, At, SEQ, CH, SEQ,
        (long long)SEQ * SEQ, (long long)CH * SEQ, (long long)SEQ * CH, 0);

    // residual: XR = rn_tf32(x + At)
    resid_round_k<<<(unsigned)((NX4 + 255) / 256), t>>>(x, At, XR, NX4);

    // out = (x+At) @ Wo^T + bo (full fp32 output)
    gemm_tf32<<<dim3(CH / BN, M / BM, 1), t, SMEMB>>>(XR, WRo, bo, out, M, CH, CH, 0, 0, 0, 0);
}